// round 2
// baseline (speedup 1.0000x reference)
#include <cuda_runtime.h>
#include <math.h>

// MoE router: logits = x @ W, softmax, top-2, dispatch.
// x: [4,4096,2048] f32 -> 16384 tokens x 2048
// W: [2048, 64] f32
// out (f32, concatenated in reference-tuple order):
//   dispatch      [16384*64]  @ 0
//   router_probs  [16384*64]  @ 1048576
//   top_k_probs   [16384*2]   @ 2097152
//   top_k_indices [16384*2]   @ 2129920   (cast to float)

#define M_TOK   16384
#define K_DIM   2048
#define N_EXP   64
#define BM      128
#define BK      32
#define THREADS 256

#define OFF_DISP  0
#define OFF_PROBS (M_TOK * N_EXP)
#define OFF_TKP   (2 * M_TOK * N_EXP)
#define OFF_TKI   (2 * M_TOK * N_EXP + 2 * M_TOK)

__device__ __forceinline__ unsigned long long pack2(float lo, float hi) {
    unsigned long long r;
    asm("mov.b64 %0, {%1, %2};" : "=l"(r) : "f"(lo), "f"(hi));
    return r;
}
__device__ __forceinline__ void unpack2(unsigned long long v, float& lo, float& hi) {
    asm("mov.b64 {%0, %1}, %2;" : "=f"(lo), "=f"(hi) : "l"(v));
}
// Packed dual-FMA: 2x fp32 FMA per instruction (sm_103a f32x2 pipe).
__device__ __forceinline__ void ffma2(unsigned long long& c, unsigned long long a,
                                      unsigned long long b) {
    asm("fma.rn.f32x2 %0, %1, %2, %0;" : "+l"(c) : "l"(a), "l"(b));
}

__global__ __launch_bounds__(THREADS, 1)
void moe_router_kernel(const float* __restrict__ x,
                       const float* __restrict__ W,
                       float* __restrict__ out) {
    // Shared buffer, dual-purpose:
    //  GEMM phase:  xs = sm[0 .. BK*132)        x tile, transposed [BK][BM+4 pad]
    //               ws = sm[BK*132 .. +BK*64)   W tile [BK][64]
    //  Epilogue:    logits [BM][65] (pad 65 -> conflict-free column scans)
    __shared__ float sm[BM * 65];            // 8320 floats = 33.3 KB
    __shared__ float s_max[BM], s_inv[BM];
    __shared__ int   s_i1[BM], s_i2[BM];

    float* xs = sm;               // stride 132 per k-row
    float* ws = sm + BK * 132;    // stride 64 per k-row

    const int t  = threadIdx.x;
    const int tx = t & 7;    // expert-pair group: experts tx*8 .. tx*8+7
    const int ty = t >> 3;   // token group: tokens ty*4 .. ty*4+3
    const int tok0 = blockIdx.x * BM;

    unsigned long long acc[16];  // [token 0..3][expert-pair 0..3], each = 2 fp32
#pragma unroll
    for (int i = 0; i < 16; i++) acc[i] = 0ull;

    for (int kt = 0; kt < K_DIM; kt += BK) {
        // --- load x tile: 128 rows x 32 k, transposed into xs[k][row] ---
#pragma unroll
        for (int r = 0; r < 4; r++) {
            int idx = t + r * THREADS;         // 0..1023
            int row = idx >> 3;                // 0..127
            int c4  = idx & 7;                 // float4 index along k
            float4 v = *reinterpret_cast<const float4*>(
                x + (size_t)(tok0 + row) * K_DIM + kt + c4 * 4);
            xs[(c4 * 4 + 0) * 132 + row] = v.x;
            xs[(c4 * 4 + 1) * 132 + row] = v.y;
            xs[(c4 * 4 + 2) * 132 + row] = v.z;
            xs[(c4 * 4 + 3) * 132 + row] = v.w;
        }
        // --- load W tile: 32 rows x 64 experts ---
#pragma unroll
        for (int r = 0; r < 2; r++) {
            int idx = t + r * THREADS;         // 0..511
            int row = idx >> 4;                // 0..31
            int c4  = idx & 15;
            *reinterpret_cast<float4*>(ws + row * 64 + c4 * 4) =
                *reinterpret_cast<const float4*>(W + (size_t)(kt + row) * N_EXP + c4 * 4);
        }
        __syncthreads();

        // --- packed-FMA mainloop ---
#pragma unroll 8
        for (int k = 0; k < BK; k++) {
            float4 xa = *reinterpret_cast<const float4*>(xs + k * 132 + ty * 4);
            unsigned long long a0 = pack2(xa.x, xa.x);
            unsigned long long a1 = pack2(xa.y, xa.y);
            unsigned long long a2 = pack2(xa.z, xa.z);
            unsigned long long a3 = pack2(xa.w, xa.w);
            const unsigned long long* wp =
                reinterpret_cast<const unsigned long long*>(ws + k * 64 + tx * 8);
            unsigned long long w0 = wp[0], w1 = wp[1], w2 = wp[2], w3 = wp[3];
            ffma2(acc[0],  a0, w0); ffma2(acc[1],  a0, w1);
            ffma2(acc[2],  a0, w2); ffma2(acc[3],  a0, w3);
            ffma2(acc[4],  a1, w0); ffma2(acc[5],  a1, w1);
            ffma2(acc[6],  a1, w2); ffma2(acc[7],  a1, w3);
            ffma2(acc[8],  a2, w0); ffma2(acc[9],  a2, w1);
            ffma2(acc[10], a2, w2); ffma2(acc[11], a2, w3);
            ffma2(acc[12], a3, w0); ffma2(acc[13], a3, w1);
            ffma2(acc[14], a3, w2); ffma2(acc[15], a3, w3);
        }
        __syncthreads();
    }

    // --- dump logits to smem [BM][65] ---
#pragma unroll
    for (int i = 0; i < 4; i++) {
#pragma unroll
        for (int j = 0; j < 4; j++) {
            float lo, hi;
            unpack2(acc[i * 4 + j], lo, hi);
            int tok = ty * 4 + i;
            int e   = tx * 8 + j * 2;
            sm[tok * 65 + e]     = lo;
            sm[tok * 65 + e + 1] = hi;
        }
    }
    __syncthreads();

    // --- phase 1: per-token max / top-2 / softmax denom ---
    if (t < BM) {
        const float* lg = sm + t * 65;
        float b1 = -INFINITY, b2 = -INFINITY;
        int i1 = 0, i2 = 0;
#pragma unroll
        for (int e = 0; e < N_EXP; e++) {
            float v = lg[e];
            if (v > b1)      { b2 = b1; i2 = i1; b1 = v; i1 = e; }
            else if (v > b2) { b2 = v;  i2 = e; }
        }
        float s = 0.f;
#pragma unroll
        for (int e = 0; e < N_EXP; e++) s += expf(lg[e] - b1);
        float inv = 1.f / s;
        s_max[t] = b1;
        s_inv[t] = inv;
        s_i1[t]  = i1;
        s_i2[t]  = i2;

        int gtok = tok0 + t;
        out[OFF_TKP + gtok * 2 + 0] = inv;                 // exp(0)*inv
        out[OFF_TKP + gtok * 2 + 1] = expf(b2 - b1) * inv;
        out[OFF_TKI + gtok * 2 + 0] = (float)i1;
        out[OFF_TKI + gtok * 2 + 1] = (float)i2;
    }
    __syncthreads();

    // --- phase 2: coalesced probs + dispatch stores ---
    for (int idx = t; idx < BM * N_EXP; idx += THREADS) {
        int tok = idx >> 6;
        int e   = idx & 63;
        float p = expf(sm[tok * 65 + e] - s_max[tok]) * s_inv[tok];
        int gtok = tok0 + tok;
        out[OFF_PROBS + gtok * N_EXP + e] = p;
        out[OFF_DISP  + gtok * N_EXP + e] =
            (e == s_i1[tok] || e == s_i2[tok]) ? 1.0f : 0.0f;
    }
}

extern "C" void kernel_launch(void* const* d_in, const int* in_sizes, int n_in,
                              void* d_out, int out_size) {
    const float* x = (const float*)d_in[0];
    const float* W = (const float*)d_in[1];
    float* out = (float*)d_out;
    moe_router_kernel<<<M_TOK / BM, THREADS>>>(x, W, out);
}

// round 3
// speedup vs baseline: 1.8017x; 1.8017x over previous
#include <cuda_runtime.h>
#include <math.h>

// MoE router: logits = x @ W, softmax, top-2, dispatch.
// x: [4,4096,2048] f32 -> 16384 tokens x 2048
// W: [2048, 64] f32
// out (f32, concatenated): dispatch[16384*64], probs[16384*64],
//                          top_k_probs[16384*2], top_k_indices[16384*2]

#define M_TOK   16384
#define K_DIM   2048
#define N_EXP   64
#define BM      64
#define BK      32
#define NTILES  (K_DIM / BK)          // 64
#define THREADS 256

#define XS_STRIDE 36                  // 32 k + 4 pad
#define XS_FLOATS (BM * XS_STRIDE)    // 2304 per stage
#define WS_FLOATS (BK * N_EXP)        // 2048 per stage
#define WS_BASE   (2 * XS_FLOATS)     // 4608
#define SM_FLOATS (WS_BASE + 2 * WS_FLOATS)   // 8704 floats = 34.8 KB

#define OFF_DISP  0
#define OFF_PROBS (M_TOK * N_EXP)
#define OFF_TKP   (2 * M_TOK * N_EXP)
#define OFF_TKI   (2 * M_TOK * N_EXP + 2 * M_TOK)

__device__ __forceinline__ unsigned long long pack2(float lo, float hi) {
    unsigned long long r;
    asm("mov.b64 %0, {%1, %2};" : "=l"(r) : "f"(lo), "f"(hi));
    return r;
}
__device__ __forceinline__ void unpack2(unsigned long long v, float& lo, float& hi) {
    asm("mov.b64 {%0, %1}, %2;" : "=f"(lo), "=f"(hi) : "l"(v));
}
__device__ __forceinline__ void ffma2(unsigned long long& c, unsigned long long a,
                                      unsigned long long b) {
    asm("fma.rn.f32x2 %0, %1, %2, %0;" : "+l"(c) : "l"(a), "l"(b));
}
__device__ __forceinline__ void cp16(unsigned dst, const void* src) {
    asm volatile("cp.async.cg.shared.global [%0], [%1], 16;\n"
                 :: "r"(dst), "l"(src));
}
#define CP_COMMIT() asm volatile("cp.async.commit_group;\n" ::: "memory")
#define CP_WAIT1()  asm volatile("cp.async.wait_group 1;\n" ::: "memory")
#define CP_WAIT0()  asm volatile("cp.async.wait_group 0;\n" ::: "memory")

__global__ __launch_bounds__(THREADS, 2)
void moe_router_kernel(const float* __restrict__ x,
                       const float* __restrict__ W,
                       float* __restrict__ out) {
    // Union: GEMM stages (xs[2] + ws[2]) / epilogue logits [BM][65]
    __shared__ float sm[SM_FLOATS];
    __shared__ float s_max[BM], s_inv[BM];
    __shared__ int   s_i1[BM], s_i2[BM];

    const int t    = threadIdx.x;
    const int tx   = t & 15;          // expert group: experts tx*4 .. tx*4+3
    const int ty   = t >> 4;          // token group:  tokens ty*4 .. ty*4+3
    const int tok0 = blockIdx.x * BM;
    const unsigned smb = (unsigned)__cvta_generic_to_shared(sm);

    // cp.async source/dest assignments (2 x-chunks + 2 w-chunks per thread)
    const int xc_tok[2] = { (t) >> 3,        (t + 256) >> 3 };
    const int xc_k4 [2] = { (t) & 7,         (t + 256) & 7 };
    const int wc_row[2] = { (t) >> 4,        (t + 256) >> 4 };
    const int wc_c4 [2] = { (t) & 15,        (t + 256) & 15 };

    unsigned long long acc[4][2];     // [token][expert-pair]
#pragma unroll
    for (int i = 0; i < 4; i++) { acc[i][0] = 0ull; acc[i][1] = 0ull; }

    // ---- prologue: stage 0 ----
#pragma unroll
    for (int r = 0; r < 2; r++) {
        cp16(smb + (unsigned)(xc_tok[r] * XS_STRIDE + xc_k4[r] * 4) * 4,
             x + (size_t)(tok0 + xc_tok[r]) * K_DIM + xc_k4[r] * 4);
        cp16(smb + (unsigned)(WS_BASE + wc_row[r] * N_EXP + wc_c4[r] * 4) * 4,
             W + (size_t)wc_row[r] * N_EXP + wc_c4[r] * 4);
    }
    CP_COMMIT();

    for (int kt = 0; kt < NTILES; kt++) {
        const int s = kt & 1;
        if (kt + 1 < NTILES) {
            const int sn = s ^ 1;
            const int kbase = (kt + 1) * BK;
#pragma unroll
            for (int r = 0; r < 2; r++) {
                cp16(smb + (unsigned)(sn * XS_FLOATS + xc_tok[r] * XS_STRIDE + xc_k4[r] * 4) * 4,
                     x + (size_t)(tok0 + xc_tok[r]) * K_DIM + kbase + xc_k4[r] * 4);
                cp16(smb + (unsigned)(WS_BASE + sn * WS_FLOATS + wc_row[r] * N_EXP + wc_c4[r] * 4) * 4,
                     W + (size_t)(kbase + wc_row[r]) * N_EXP + wc_c4[r] * 4);
            }
            CP_COMMIT();
            CP_WAIT1();
        } else {
            CP_WAIT0();
        }
        __syncthreads();

        const float* xsp = sm + s * XS_FLOATS + (ty * 4) * XS_STRIDE;
        const float* wsp = sm + WS_BASE + s * WS_FLOATS + tx * 4;

#pragma unroll
        for (int k4 = 0; k4 < BK / 4; k4++) {
            float xr[4][4];
#pragma unroll
            for (int i = 0; i < 4; i++) {
                float4 v = *reinterpret_cast<const float4*>(xsp + i * XS_STRIDE + k4 * 4);
                xr[i][0] = v.x; xr[i][1] = v.y; xr[i][2] = v.z; xr[i][3] = v.w;
            }
#pragma unroll
            for (int kk = 0; kk < 4; kk++) {
                ulonglong2 w = *reinterpret_cast<const ulonglong2*>(
                    wsp + (k4 * 4 + kk) * N_EXP);
#pragma unroll
                for (int i = 0; i < 4; i++) {
                    unsigned long long a = pack2(xr[i][kk], xr[i][kk]);
                    ffma2(acc[i][0], a, w.x);
                    ffma2(acc[i][1], a, w.y);
                }
            }
        }
        __syncthreads();
    }

    // ---- dump logits to smem [BM][65] ----
#pragma unroll
    for (int i = 0; i < 4; i++) {
        int tok = ty * 4 + i;
        float e0, e1, e2, e3;
        unpack2(acc[i][0], e0, e1);
        unpack2(acc[i][1], e2, e3);
        sm[tok * 65 + tx * 4 + 0] = e0;
        sm[tok * 65 + tx * 4 + 1] = e1;
        sm[tok * 65 + tx * 4 + 2] = e2;
        sm[tok * 65 + tx * 4 + 3] = e3;
    }
    __syncthreads();

    // ---- phase 1: per-token max / top-2 / softmax denom ----
    if (t < BM) {
        const float* lg = sm + t * 65;
        float b1 = -INFINITY, b2 = -INFINITY;
        int i1 = 0, i2 = 0;
#pragma unroll
        for (int e = 0; e < N_EXP; e++) {
            float v = lg[e];
            if (v > b1)      { b2 = b1; i2 = i1; b1 = v; i1 = e; }
            else if (v > b2) { b2 = v;  i2 = e; }
        }
        float ssum = 0.f;
#pragma unroll
        for (int e = 0; e < N_EXP; e++) ssum += __expf(lg[e] - b1);
        float inv = 1.f / ssum;
        s_max[t] = b1;
        s_inv[t] = inv;
        s_i1[t]  = i1;
        s_i2[t]  = i2;

        int gtok = tok0 + t;
        out[OFF_TKP + gtok * 2 + 0] = inv;
        out[OFF_TKP + gtok * 2 + 1] = __expf(b2 - b1) * inv;
        out[OFF_TKI + gtok * 2 + 0] = (float)i1;
        out[OFF_TKI + gtok * 2 + 1] = (float)i2;
    }
    __syncthreads();

    // ---- phase 2: coalesced probs + dispatch ----
#pragma unroll
    for (int idx = t; idx < BM * N_EXP; idx += THREADS) {
        int tok = idx >> 6;
        int e   = idx & 63;
        float p = __expf(sm[tok * 65 + e] - s_max[tok]) * s_inv[tok];
        int gtok = tok0 + tok;
        out[OFF_PROBS + gtok * N_EXP + e] = p;
        out[OFF_DISP  + gtok * N_EXP + e] =
            (e == s_i1[tok] || e == s_i2[tok]) ? 1.0f : 0.0f;
    }
}

extern "C" void kernel_launch(void* const* d_in, const int* in_sizes, int n_in,
                              void* d_out, int out_size) {
    const float* x = (const float*)d_in[0];
    const float* W = (const float*)d_in[1];
    float* out = (float*)d_out;
    moe_router_kernel<<<M_TOK / BM, THREADS>>>(x, W, out);
}

// round 5
// speedup vs baseline: 2.0787x; 1.1538x over previous
#include <cuda_runtime.h>
#include <math.h>

// MoE router, 2-kernel k-split version.
// K1: partial logits  x[16384,2048] @ W[2048,64], K split 4 ways -> g_partial
// K2: warp-per-token reduce + softmax + top2 + all 4 outputs
//
// out (f32, concatenated): dispatch[16384*64], probs[16384*64],
//                          top_k_probs[16384*2], top_k_indices[16384*2]

#define M_TOK   16384
#define K_DIM   2048
#define N_EXP   64
#define KSPLIT  4
#define KSL     (K_DIM / KSPLIT)      // 512
#define BM      256
#define BK      32
#define NT      (KSL / BK)            // 16 tiles per CTA
#define THREADS 256

#define XS_STRIDE 36                  // 32 k + 4 pad (bank-rotate per token)
#define XS_FLOATS (BM * XS_STRIDE)    // 9216 per stage
#define WS_FLOATS (BK * N_EXP)        // 2048 per stage
#define WS_BASE   (2 * XS_FLOATS)     // 18432
#define SM_FLOATS (WS_BASE + 2 * WS_FLOATS)   // 22528 floats = 90112 B
#define SMEM_BYTES (SM_FLOATS * 4)

#define OFF_DISP  0
#define OFF_PROBS (M_TOK * N_EXP)
#define OFF_TKP   (2 * M_TOK * N_EXP)
#define OFF_TKI   (2 * M_TOK * N_EXP + 2 * M_TOK)

__device__ float g_partial[KSPLIT * M_TOK * N_EXP];   // 16.8 MB scratch

__device__ __forceinline__ unsigned long long pack2(float v) {
    unsigned long long r;
    asm("mov.b64 %0, {%1, %1};" : "=l"(r) : "f"(v));
    return r;
}
__device__ __forceinline__ void unpack2(unsigned long long v, float& lo, float& hi) {
    asm("mov.b64 {%0, %1}, %2;" : "=f"(lo), "=f"(hi) : "l"(v));
}
__device__ __forceinline__ void ffma2(unsigned long long& c, unsigned long long a,
                                      unsigned long long b) {
    asm("fma.rn.f32x2 %0, %1, %2, %0;" : "+l"(c) : "l"(a), "l"(b));
}
__device__ __forceinline__ void cp16(unsigned dst, const void* src) {
    asm volatile("cp.async.cg.shared.global [%0], [%1], 16;\n" :: "r"(dst), "l"(src));
}
#define CP_COMMIT() asm volatile("cp.async.commit_group;\n" ::: "memory")
#define CP_WAIT1()  asm volatile("cp.async.wait_group 1;\n" ::: "memory")
#define CP_WAIT0()  asm volatile("cp.async.wait_group 0;\n" ::: "memory")

// ======================= kernel 1: partial GEMM =======================
__global__ __launch_bounds__(THREADS, 2)
void moe_gemm_kernel(const float* __restrict__ x,
                     const float* __restrict__ W) {
    extern __shared__ float sm[];

    const int t  = threadIdx.x;
    const int tx = t & 3;             // expert chunks: j*16 + tx*4 .. +3, j=0..3
    const int ty = t >> 2;            // tokens: ty + i*64, i=0..3
    const int mt = blockIdx.x & 63;
    const int ks = blockIdx.x >> 6;
    const int tok0  = mt * BM;
    const int kbase = ks * KSL;
    const unsigned smb = (unsigned)__cvta_generic_to_shared(sm);

    // cp.async assignments: x = 8 chunks/thread, W = 2 chunks/thread
    int xc_tok[8], xc_c[8];
#pragma unroll
    for (int r = 0; r < 8; r++) {
        int idx = t + r * THREADS;    // 0..2047
        xc_tok[r] = idx >> 3;         // 0..255
        xc_c[r]   = idx & 7;          // float4 within 32-k row
    }
    const int wc_row0 = t >> 4, wc_c0 = t & 15;             // chunk 0
    const int wc_row1 = (t + 256) >> 4, wc_c1 = (t + 256) & 15;

    unsigned long long acc[4][8];     // [token i][expert pair]
#pragma unroll
    for (int i = 0; i < 4; i++)
#pragma unroll
        for (int p = 0; p < 8; p++) acc[i][p] = 0ull;

    // ---- prologue: stage 0 ----
#pragma unroll
    for (int r = 0; r < 8; r++)
        cp16(smb + (unsigned)(xc_tok[r] * XS_STRIDE + xc_c[r] * 4) * 4,
             x + (size_t)(tok0 + xc_tok[r]) * K_DIM + kbase + xc_c[r] * 4);
    cp16(smb + (unsigned)(WS_BASE + wc_row0 * N_EXP + wc_c0 * 4) * 4,
         W + (size_t)(kbase + wc_row0) * N_EXP + wc_c0 * 4);
    cp16(smb + (unsigned)(WS_BASE + wc_row1 * N_EXP + wc_c1 * 4) * 4,
         W + (size_t)(kbase + wc_row1) * N_EXP + wc_c1 * 4);
    CP_COMMIT();

#pragma unroll 1
    for (int kt = 0; kt < NT; kt++) {
        const int s = kt & 1;
        if (kt + 1 < NT) {
            const int sn = s ^ 1;
            const int kb = kbase + (kt + 1) * BK;
#pragma unroll
            for (int r = 0; r < 8; r++)
                cp16(smb + (unsigned)(sn * XS_FLOATS + xc_tok[r] * XS_STRIDE + xc_c[r] * 4) * 4,
                     x + (size_t)(tok0 + xc_tok[r]) * K_DIM + kb + xc_c[r] * 4);
            cp16(smb + (unsigned)(WS_BASE + sn * WS_FLOATS + wc_row0 * N_EXP + wc_c0 * 4) * 4,
                 W + (size_t)(kb + wc_row0) * N_EXP + wc_c0 * 4);
            cp16(smb + (unsigned)(WS_BASE + sn * WS_FLOATS + wc_row1 * N_EXP + wc_c1 * 4) * 4,
                 W + (size_t)(kb + wc_row1) * N_EXP + wc_c1 * 4);
            CP_COMMIT();
            CP_WAIT1();
        } else {
            CP_WAIT0();
        }
        __syncthreads();

        const float* xsp = sm + s * XS_FLOATS + ty * XS_STRIDE;
        const float* wsp = sm + WS_BASE + s * WS_FLOATS + tx * 4;

#pragma unroll
        for (int k4 = 0; k4 < BK / 4; k4++) {
            float4 xv[4];
#pragma unroll
            for (int i = 0; i < 4; i++)
                xv[i] = *reinterpret_cast<const float4*>(xsp + i * 64 * XS_STRIDE + k4 * 4);
#pragma unroll
            for (int kk = 0; kk < 4; kk++) {
                const float* wrow = wsp + (k4 * 4 + kk) * N_EXP;
                ulonglong2 w0 = *reinterpret_cast<const ulonglong2*>(wrow);
                ulonglong2 w1 = *reinterpret_cast<const ulonglong2*>(wrow + 16);
                ulonglong2 w2 = *reinterpret_cast<const ulonglong2*>(wrow + 32);
                ulonglong2 w3 = *reinterpret_cast<const ulonglong2*>(wrow + 48);
#pragma unroll
                for (int i = 0; i < 4; i++) {
                    float xs4 = (kk == 0) ? xv[i].x : (kk == 1) ? xv[i].y
                              : (kk == 2) ? xv[i].z : xv[i].w;
                    unsigned long long a = pack2(xs4);
                    ffma2(acc[i][0], a, w0.x); ffma2(acc[i][1], a, w0.y);
                    ffma2(acc[i][2], a, w1.x); ffma2(acc[i][3], a, w1.y);
                    ffma2(acc[i][4], a, w2.x); ffma2(acc[i][5], a, w2.y);
                    ffma2(acc[i][6], a, w3.x); ffma2(acc[i][7], a, w3.y);
                }
            }
        }
        __syncthreads();
    }

    // ---- store partial logits ----
    float* pout = g_partial + (size_t)ks * M_TOK * N_EXP;
#pragma unroll
    for (int i = 0; i < 4; i++) {
        int tok = tok0 + ty + i * 64;
#pragma unroll
        for (int j = 0; j < 4; j++) {
            float4 v;
            unpack2(acc[i][2 * j],     v.x, v.y);
            unpack2(acc[i][2 * j + 1], v.z, v.w);
            *reinterpret_cast<float4*>(pout + (size_t)tok * N_EXP + j * 16 + tx * 4) = v;
        }
    }
}

// ================ kernel 2: reduce + softmax + top2 ================
__global__ __launch_bounds__(256)
void moe_reduce_kernel(float* __restrict__ out) {
    const int tok  = (blockIdx.x * 256 + threadIdx.x) >> 5;
    const int lane = threadIdx.x & 31;

    float l0 = 0.f, l1 = 0.f;
#pragma unroll
    for (int s = 0; s < KSPLIT; s++) {
        const float* p = g_partial + (size_t)s * M_TOK * N_EXP + (size_t)tok * N_EXP;
        l0 += p[lane];
        l1 += p[lane + 32];
    }

    // per-lane sorted top-2 (lower index wins ties, matching lax.top_k)
    float b1, b2; int j1, j2;
    if (l0 >= l1) { b1 = l0; j1 = lane;      b2 = l1; j2 = lane + 32; }
    else          { b1 = l1; j1 = lane + 32; b2 = l0; j2 = lane; }

#pragma unroll
    for (int off = 16; off > 0; off >>= 1) {
        float c1 = __shfl_xor_sync(0xffffffff, b1, off);
        int   k1 = __shfl_xor_sync(0xffffffff, j1, off);
        float c2 = __shfl_xor_sync(0xffffffff, b2, off);
        int   k2 = __shfl_xor_sync(0xffffffff, j2, off);
        bool aw = (b1 > c1) || (b1 == c1 && j1 < k1);
        float n1  = aw ? b1 : c1;  int m1  = aw ? j1 : k1;
        float cv  = aw ? c1 : b1;  int ci  = aw ? k1 : j1;
        float sv  = aw ? b2 : c2;  int si  = aw ? j2 : k2;
        bool cw = (cv > sv) || (cv == sv && ci < si);
        b1 = n1; j1 = m1;
        b2 = cw ? cv : sv; j2 = cw ? ci : si;
    }

    float e0 = __expf(l0 - b1);
    float e1 = __expf(l1 - b1);
    float ssum = e0 + e1;
#pragma unroll
    for (int off = 16; off > 0; off >>= 1)
        ssum += __shfl_xor_sync(0xffffffff, ssum, off);
    float inv = 1.f / ssum;

    size_t rbase = (size_t)tok * N_EXP;
    out[OFF_PROBS + rbase + lane]      = e0 * inv;
    out[OFF_PROBS + rbase + lane + 32] = e1 * inv;
    out[OFF_DISP  + rbase + lane]      = (lane == j1 || lane == j2) ? 1.f : 0.f;
    out[OFF_DISP  + rbase + lane + 32] = (lane + 32 == j1 || lane + 32 == j2) ? 1.f : 0.f;
    if (lane == 0) {
        out[OFF_TKP + tok * 2 + 0] = inv;                     // exp(b1-b1)*inv
        out[OFF_TKP + tok * 2 + 1] = __expf(b2 - b1) * inv;
        out[OFF_TKI + tok * 2 + 0] = (float)j1;
        out[OFF_TKI + tok * 2 + 1] = (float)j2;
    }
}

extern "C" void kernel_launch(void* const* d_in, const int* in_sizes, int n_in,
                              void* d_out, int out_size) {
    const float* x = (const float*)d_in[0];
    const float* W = (const float*)d_in[1];
    float* out = (float*)d_out;

    static bool attr_set = false;
    if (!attr_set) {
        cudaFuncSetAttribute(moe_gemm_kernel,
                             cudaFuncAttributeMaxDynamicSharedMemorySize, SMEM_BYTES);
        attr_set = true;
    }

    moe_gemm_kernel<<<(M_TOK / BM) * KSPLIT, THREADS, SMEM_BYTES>>>(x, W);
    moe_reduce_kernel<<<M_TOK / 8, 256>>>(out);
}